// round 1
// baseline (speedup 1.0000x reference)
#include <cuda_runtime.h>

#define BB 8
#define EE 64
#define MM 128
#define DD 256
#define HH 8
#define DKK 32
#define NPAIR (EE*EE)
#define SETHALF (BB*NPAIR*DD)
#define CHUNK 16

// ---------------- scratch (device globals; no allocation allowed) ----------------
__device__ float g_msr[BB*MM*DD];          // gathered mention_sen_rep
__device__ float g_q[2][BB*EE*DD];         // projected entity queries (set 0=h, 1=t)
__device__ float g_k[2][BB*MM*DD];         // projected keys (from msr)
__device__ float g_v[2][BB*MM*DD];         // projected values (from mentions)
__device__ float g_u[2][BB*HH*MM*DD];      // u[h,m,:] = v_h[m] @ Wo_h  (Wo folded in)
__device__ float g_S[2][BB*HH*EE*MM];      // scores [b,h,query_entity,m]
__device__ float g_usum[2][BB*DD];         // sum_{h,m} u  (for empty-mask uniform case)
__device__ int   g_cnt[BB*EE];             // mentions per entity
__device__ int   g_list[BB*EE*MM];         // mention index lists

// ---------------- gather mention_sen_rep = sentences[b, sent_ids[b,m]] ----------------
__global__ void k_gather(const float* __restrict__ sentences, const int* __restrict__ sent_ids) {
    int m = blockIdx.x, b = blockIdx.y;
    int sid = sent_ids[b*MM + m];
    const float4* src = (const float4*)(sentences + ((size_t)b*32 + sid)*DD);
    float4* dst = (float4*)(g_msr + ((size_t)b*MM + m)*DD);
    dst[threadIdx.x] = src[threadIdx.x];
}

// ---------------- per-(b,entity) mention lists ----------------
__global__ void k_lists(const int* __restrict__ eid) {
    int b = blockIdx.x;
    int e = threadIdx.x;  // 64 threads
    int cnt = 0;
    for (int m = 0; m < MM; m++) {
        if (eid[b*MM + m] == e) g_list[(b*EE + e)*MM + cnt++] = m;
    }
    g_cnt[b*EE + e] = cnt;
}

// ---------------- all six 256x256 projections in ONE launch (fills the chip) ----------
// grid (2 colTiles, 20 rowTiles-flattened-over-jobs, B). Tile = 32 rows x 128 cols, K=256.
__global__ __launch_bounds__(256) void k_gemm_all(
    const float* __restrict__ entities, const float* __restrict__ mentions,
    const float* __restrict__ W_h, const float* __restrict__ b_h,
    const float* __restrict__ W_t, const float* __restrict__ b_t)
{
    __shared__ float a_sh[32][32];    // [kk][row]
    __shared__ float w_sh[32][128];   // [kk][col]
    int b = blockIdx.z;
    int y = blockIdx.y;
    int colTile = blockIdx.x;
    int job, rowTile;
    if (y < 4)       { job = y >> 1;            rowTile = y & 1; }
    else if (y < 12) { job = 2 + ((y-4) >> 2);  rowTile = (y-4) & 3; }
    else             { job = 4 + ((y-12) >> 2); rowTile = (y-12) & 3; }
    const float* A; const float* W; const float* bias; float* C; int rows;
    switch (job) {
      case 0:  A = entities; W = W_h;          bias = b_h;       C = g_q[0]; rows = EE; break;
      case 1:  A = entities; W = W_t;          bias = b_t;       C = g_q[1]; rows = EE; break;
      case 2:  A = g_msr;    W = W_h + 65536;  bias = b_h + 256; C = g_k[0]; rows = MM; break;
      case 3:  A = g_msr;    W = W_t + 65536;  bias = b_t + 256; C = g_k[1]; rows = MM; break;
      case 4:  A = mentions; W = W_h + 131072; bias = b_h + 512; C = g_v[0]; rows = MM; break;
      default: A = mentions; W = W_t + 131072; bias = b_t + 512; C = g_v[1]; rows = MM; break;
    }
    int row0 = rowTile * 32;
    int col0 = colTile * 128;
    const float* Ab = A + ((size_t)b * rows + row0) * DD;
    int tid = threadIdx.x;
    int rg = tid & 7, cg = tid >> 3;
    float acc[4][4] = {};
    for (int kc = 0; kc < 8; kc++) {
        int k0 = kc * 32;
        {   // A tile, transposed into smem
            int r = tid >> 3;
            int kq = (tid & 7) * 4;
            float4 av = *(const float4*)(Ab + r * DD + k0 + kq);
            a_sh[kq+0][r] = av.x; a_sh[kq+1][r] = av.y;
            a_sh[kq+2][r] = av.z; a_sh[kq+3][r] = av.w;
        }
        #pragma unroll
        for (int i = 0; i < 4; i++) {   // W tile, coalesced float4
            int idx = tid + i * 256;
            int kk = idx >> 5;
            int dq = (idx & 31) * 4;
            *(float4*)&w_sh[kk][dq] = *(const float4*)(W + (size_t)(k0 + kk) * DD + col0 + dq);
        }
        __syncthreads();
        #pragma unroll
        for (int kk = 0; kk < 32; kk++) {
            float4 av = *(const float4*)&a_sh[kk][rg * 4];
            float4 wv = *(const float4*)&w_sh[kk][cg * 4];
            float aa[4] = {av.x, av.y, av.z, av.w};
            float ww[4] = {wv.x, wv.y, wv.z, wv.w};
            #pragma unroll
            for (int r = 0; r < 4; r++)
                #pragma unroll
                for (int c = 0; c < 4; c++)
                    acc[r][c] = fmaf(aa[r], ww[c], acc[r][c]);
        }
        __syncthreads();
    }
    #pragma unroll
    for (int r = 0; r < 4; r++) {
        int row = row0 + rg * 4 + r;
        int col = col0 + cg * 4;
        float4 o;
        o.x = acc[r][0] + bias[col + 0];
        o.y = acc[r][1] + bias[col + 1];
        o.z = acc[r][2] + bias[col + 2];
        o.w = acc[r][3] + bias[col + 3];
        *(float4*)(C + ((size_t)b * rows + row) * DD + col) = o;
    }
}

// ---------------- u[s][b][h][m][d] = sum_c v[b][m][h*32+c] * Wo[h*32+c][d] ----------
// grid (2 colTiles, 4 rowTiles, 2*B*H). Tile 32 rows x 128 cols, K=32 (single chunk).
__global__ __launch_bounds__(256) void k_uproj(const float* __restrict__ W_h,
                                               const float* __restrict__ W_t)
{
    __shared__ float a_sh[32][32];
    __shared__ float w_sh[32][128];
    int z = blockIdx.z;
    int s = z >> 6;
    int b = (z >> 3) & 7;
    int h = z & 7;
    const float* Wo = (s ? W_t : W_h) + 3 * 65536;
    int colTile = blockIdx.x, rowTile = blockIdx.y;
    int row0 = rowTile * 32;
    int col0 = colTile * 128;
    const float* Ab = g_v[s] + ((size_t)(b * MM) + row0) * DD + h * DKK;
    int tid = threadIdx.x;
    int rg = tid & 7, cg = tid >> 3;
    {
        int r = tid >> 3;
        int kq = (tid & 7) * 4;
        float4 av = *(const float4*)(Ab + r * DD + kq);
        a_sh[kq+0][r] = av.x; a_sh[kq+1][r] = av.y;
        a_sh[kq+2][r] = av.z; a_sh[kq+3][r] = av.w;
    }
    #pragma unroll
    for (int i = 0; i < 4; i++) {
        int idx = tid + i * 256;
        int kk = idx >> 5;
        int dq = (idx & 31) * 4;
        *(float4*)&w_sh[kk][dq] = *(const float4*)(Wo + (size_t)(h*DKK + kk) * DD + col0 + dq);
    }
    __syncthreads();
    float acc[4][4] = {};
    #pragma unroll
    for (int kk = 0; kk < 32; kk++) {
        float4 av = *(const float4*)&a_sh[kk][rg * 4];
        float4 wv = *(const float4*)&w_sh[kk][cg * 4];
        float aa[4] = {av.x, av.y, av.z, av.w};
        float ww[4] = {wv.x, wv.y, wv.z, wv.w};
        #pragma unroll
        for (int r = 0; r < 4; r++)
            #pragma unroll
            for (int c = 0; c < 4; c++)
                acc[r][c] = fmaf(aa[r], ww[c], acc[r][c]);
    }
    float* U = g_u[s] + ((size_t)(b*HH + h) * MM) * DD;
    #pragma unroll
    for (int r = 0; r < 4; r++) {
        int row = row0 + rg * 4 + r;
        int col = col0 + cg * 4;
        float4 o = make_float4(acc[r][0], acc[r][1], acc[r][2], acc[r][3]);
        *(float4*)(U + (size_t)row * DD + col) = o;
    }
}

// ------- usum[s][b][d] = sum_{h,m} u = (sum_m v[b,m,:]) @ Wo  (cheap form) -------
__global__ void k_usum(const float* __restrict__ W_h, const float* __restrict__ W_t) {
    int b = blockIdx.x, s = blockIdx.y;
    const float* Wo = (s ? W_t : W_h) + 3 * 65536;
    __shared__ float vs[DD];
    int d = threadIdx.x;
    const float* v = g_v[s] + (size_t)b * MM * DD;
    float sum = 0.f;
    for (int m = 0; m < MM; m++) sum += v[m * DD + d];
    vs[d] = sum;
    __syncthreads();
    float o = 0.f;
    for (int k = 0; k < DD; k++) o = fmaf(vs[k], Wo[(size_t)k * DD + d], o);
    g_usum[s][b * DD + d] = o;
}

// ---------------- scores: S[s][b][h][j][m] = q_j . k_m / sqrt(32) ----------------
__global__ __launch_bounds__(256) void k_scores() {
    int h = blockIdx.x, b = blockIdx.y, s = blockIdx.z;
    __shared__ float qs[EE][DKK + 1];
    __shared__ float ks[MM][DKK + 1];
    const float* q = g_q[s] + (size_t)b * EE * DD + h * DKK;
    const float* k = g_k[s] + (size_t)b * MM * DD + h * DKK;
    int tid = threadIdx.x;
    for (int i = tid; i < EE * DKK; i += 256) { int r = i >> 5, c = i & 31; qs[r][c] = q[r * DD + c]; }
    for (int i = tid; i < MM * DKK; i += 256) { int r = i >> 5, c = i & 31; ks[r][c] = k[r * DD + c]; }
    __syncthreads();
    int j = tid >> 2;
    float* Srow = g_S[s] + ((size_t)(b * HH + h) * EE + j) * MM;
    const float scale = 0.17677669529663687f;  // 1/sqrt(32)
    for (int m = (tid & 3); m < MM; m += 4) {
        float acc = 0.f;
        #pragma unroll
        for (int c = 0; c < DKK; c++) acc = fmaf(qs[j][c], ks[m][c], acc);
        Srow[m] = acc * scale;
    }
}

// ---------------- main: masked softmax over mention list + weighted-u accumulate ----
// grid (E mask-entities, B, 2 sets), block 256. Each block writes a 64x256 out tile.
__global__ __launch_bounds__(256) void k_out(const float* __restrict__ b_h,
                                             const float* __restrict__ b_t,
                                             float* __restrict__ out)
{
    int i = blockIdx.x;   // mask entity
    int b = blockIdx.y;
    int s = blockIdx.z;
    const float* bo = (s ? b_t : b_h) + 3 * 256;
    float* outS = out + (size_t)s * SETHALF + (size_t)b * NPAIR * DD;
    int tid = threadIdx.x;
    int cnt = g_cnt[b * EE + i];

    if (cnt == 0) {
        // all-masked => softmax of equal -1e9 values is exactly uniform 1/128
        int d = tid;
        float val = bo[d] + g_usum[s][b * DD + d] * (1.0f / 128.0f);
        for (int j = 0; j < EE; j++) {
            int pair = (s == 0) ? (i * EE + j) : (j * EE + i);
            outS[(size_t)pair * DD + d] = val;
        }
        return;
    }

    __shared__ float mx[HH][EE];
    __shared__ float rse[HH][EE];
    __shared__ float wsh[HH][CHUNK][EE];
    __shared__ int lst[MM];
    for (int t = tid; t < cnt; t += 256) lst[t] = g_list[(b * EE + i) * MM + t];
    __syncthreads();

    // softmax stats per (query j, head h) over the mention list
    for (int task = tid; task < HH * EE; task += 256) {
        int h = task >> 6, j = task & 63;
        const float* Srow = g_S[s] + ((size_t)(b * HH + h) * EE + j) * MM;
        float m_ = -1e30f;
        for (int c = 0; c < cnt; c++) m_ = fmaxf(m_, Srow[lst[c]]);
        float se = 0.f;
        for (int c = 0; c < cnt; c++) se += __expf(Srow[lst[c]] - m_);
        mx[h][j] = m_;
        rse[h][j] = 1.0f / se;
    }
    __syncthreads();

    int dq = tid & 63;   // d = dq*4 .. dq*4+3
    int jg = tid >> 6;   // query group: j = jg*16 .. +15
    float acc[16][4];
    #pragma unroll
    for (int jj = 0; jj < 16; jj++) {
        acc[jj][0] = 0.f; acc[jj][1] = 0.f; acc[jj][2] = 0.f; acc[jj][3] = 0.f;
    }

    for (int base = 0; base < cnt; base += CHUNK) {
        int cEnd = min(CHUNK, cnt - base);
        int ce64 = cEnd << 6;
        for (int t = tid; t < HH * ce64; t += 256) {
            int h = t / ce64;
            int rem = t - h * ce64;
            int c = rem >> 6;
            int j = rem & 63;
            int m_ = lst[base + c];
            float sv = g_S[s][((size_t)(b * HH + h) * EE + j) * MM + m_];
            wsh[h][c][j] = __expf(sv - mx[h][j]) * rse[h][j];
        }
        __syncthreads();
        for (int h = 0; h < HH; h++) {
            for (int c = 0; c < cEnd; c++) {
                int m_ = lst[base + c];
                float4 u4 = *(const float4*)(g_u[s] +
                        ((size_t)(b * HH + h) * MM + m_) * DD + dq * 4);
                const float* wrow = &wsh[h][c][jg * 16];
                #pragma unroll
                for (int jj = 0; jj < 16; jj++) {
                    float w = wrow[jj];
                    acc[jj][0] = fmaf(w, u4.x, acc[jj][0]);
                    acc[jj][1] = fmaf(w, u4.y, acc[jj][1]);
                    acc[jj][2] = fmaf(w, u4.z, acc[jj][2]);
                    acc[jj][3] = fmaf(w, u4.w, acc[jj][3]);
                }
            }
        }
        __syncthreads();
    }

    float4 bo4 = *(const float4*)(bo + dq * 4);
    #pragma unroll
    for (int jj = 0; jj < 16; jj++) {
        int j = jg * 16 + jj;
        int pair = (s == 0) ? (i * EE + j) : (j * EE + i);
        float4 o;
        o.x = acc[jj][0] + bo4.x;
        o.y = acc[jj][1] + bo4.y;
        o.z = acc[jj][2] + bo4.z;
        o.w = acc[jj][3] + bo4.w;
        *(float4*)(outS + (size_t)pair * DD + dq * 4) = o;
    }
}

// ---------------- launch ----------------
extern "C" void kernel_launch(void* const* d_in, const int* in_sizes, int n_in,
                              void* d_out, int out_size) {
    const float* entities  = (const float*)d_in[0];
    const float* mentions  = (const float*)d_in[1];
    const float* sentences = (const float*)d_in[2];
    const int*   sent_ids  = (const int*)d_in[3];
    const int*   eid       = (const int*)d_in[4];
    const float* W_h       = (const float*)d_in[5];
    const float* b_h       = (const float*)d_in[6];
    const float* W_t       = (const float*)d_in[7];
    const float* b_t       = (const float*)d_in[8];
    float* out = (float*)d_out;

    k_gather<<<dim3(MM, BB), 64>>>(sentences, sent_ids);
    k_lists<<<BB, 64>>>(eid);
    k_gemm_all<<<dim3(2, 20, BB), 256>>>(entities, mentions, W_h, b_h, W_t, b_t);
    k_uproj<<<dim3(2, 4, 2 * BB * HH), 256>>>(W_h, W_t);
    k_usum<<<dim3(BB, 2), 256>>>(W_h, W_t);
    k_scores<<<dim3(HH, BB, 2), 256>>>();
    k_out<<<dim3(EE, BB, 2), 256>>>(b_h, b_t, out);
}

// round 2
// speedup vs baseline: 1.0416x; 1.0416x over previous
#include <cuda_runtime.h>

#define BB 8
#define EE 64
#define MM 128
#define DD 256
#define HH 8
#define DKK 32
#define NPAIR (EE*EE)
#define SETHALF (BB*NPAIR*DD)
#define CHUNK 16

typedef unsigned long long ull;

// ---- packed fp32x2 helpers (FFMA2: 2x fp32 throughput, ptxas never auto-emits) ----
__device__ __forceinline__ void fma2(ull &d, ull a, ull b) {
    asm("fma.rn.f32x2 %0, %1, %2, %0;" : "+l"(d) : "l"(a), "l"(b));
}
__device__ __forceinline__ ull bcast2(float x) {
    ull d;
    asm("mov.b64 %0, {%1, %1};" : "=l"(d) : "r"(__float_as_uint(x)));
    return d;
}
__device__ __forceinline__ float2 unpack2(ull v) {
    float2 r;
    asm("mov.b64 {%0, %1}, %2;" : "=f"(r.x), "=f"(r.y) : "l"(v));
    return r;
}

// ---------------- scratch ----------------
__device__ float g_msr[BB*MM*DD];
__device__ float g_q[2][BB*EE*DD];
__device__ float g_k[2][BB*MM*DD];
__device__ float g_v[2][BB*MM*DD];
__device__ float g_u[2][BB*HH*MM*DD];
__device__ float g_S[2][BB*HH*EE*MM];
__device__ float g_usum[2][BB*DD];
__device__ int   g_cnt[BB*EE];
__device__ int   g_list[BB*EE*MM];

// ---------------- prep: gather msr + entity mention lists (fused) ----------------
__global__ void k_prep(const float* __restrict__ sentences,
                       const int* __restrict__ sent_ids,
                       const int* __restrict__ eid) {
    int blk = blockIdx.x;
    if (blk < BB * MM) {
        int b = blk >> 7, m = blk & 127;
        int sid = sent_ids[b*MM + m];
        const float4* src = (const float4*)(sentences + ((size_t)b*32 + sid)*DD);
        float4* dst = (float4*)(g_msr + ((size_t)b*MM + m)*DD);
        dst[threadIdx.x] = src[threadIdx.x];
    } else {
        int b = blk - BB * MM;
        int e = threadIdx.x;
        int cnt = 0;
        for (int m = 0; m < MM; m++)
            if (eid[b*MM + m] == e) g_list[(b*EE + e)*MM + cnt++] = m;
        g_cnt[b*EE + e] = cnt;
    }
}

// ---------------- six projections, 64x128 tiles, 8x4/thread, f32x2 ----------------
__global__ __launch_bounds__(256) void k_gemm_all(
    const float* __restrict__ entities, const float* __restrict__ mentions,
    const float* __restrict__ W_h, const float* __restrict__ b_h,
    const float* __restrict__ W_t, const float* __restrict__ b_t)
{
    __shared__ float a_sh[32][68];    // [k][row], padded stride (16B-aligned rows)
    __shared__ float w_sh[32][128];   // [k][col]
    int b = blockIdx.z;
    int y = blockIdx.y;
    int colTile = blockIdx.x;
    int job, rowTile;
    if (y < 2) { job = y; rowTile = 0; }
    else       { job = 2 + ((y - 2) >> 1); rowTile = (y - 2) & 1; }
    const float* A; const float* W; const float* bias; float* C; int rows;
    switch (job) {
      case 0:  A = entities; W = W_h;          bias = b_h;       C = g_q[0]; rows = EE; break;
      case 1:  A = entities; W = W_t;          bias = b_t;       C = g_q[1]; rows = EE; break;
      case 2:  A = g_msr;    W = W_h + 65536;  bias = b_h + 256; C = g_k[0]; rows = MM; break;
      case 3:  A = g_msr;    W = W_t + 65536;  bias = b_t + 256; C = g_k[1]; rows = MM; break;
      case 4:  A = mentions; W = W_h + 131072; bias = b_h + 512; C = g_v[0]; rows = MM; break;
      default: A = mentions; W = W_t + 131072; bias = b_t + 512; C = g_v[1]; rows = MM; break;
    }
    int row0 = rowTile * 64;
    int col0 = colTile * 128;
    const float* Ab = A + ((size_t)b * rows + row0) * DD;
    int tid = threadIdx.x;
    int rg = tid & 7;    // 8 row groups x 8 rows
    int cg = tid >> 3;   // 32 col groups x 4 cols
    ull acc[4][4];
    #pragma unroll
    for (int p = 0; p < 4; p++)
        #pragma unroll
        for (int c = 0; c < 4; c++) acc[p][c] = 0ull;

    for (int kc = 0; kc < 8; kc++) {
        int k0 = kc * 32;
        #pragma unroll
        for (int i = 0; i < 2; i++) {     // A: 64x32 transposed
            int f = tid * 2 + i;
            int r = f >> 3;
            int kq = (f & 7) * 4;
            float4 av = *(const float4*)(Ab + (size_t)r * DD + k0 + kq);
            a_sh[kq+0][r] = av.x; a_sh[kq+1][r] = av.y;
            a_sh[kq+2][r] = av.z; a_sh[kq+3][r] = av.w;
        }
        #pragma unroll
        for (int i = 0; i < 4; i++) {     // W: 32x128 coalesced
            int idx = tid + i * 256;
            int kk = idx >> 5;
            int dq = (idx & 31) * 4;
            *(float4*)&w_sh[kk][dq] = *(const float4*)(W + (size_t)(k0 + kk) * DD + col0 + dq);
        }
        __syncthreads();
        #pragma unroll
        for (int kk = 0; kk < 32; kk++) {
            ulonglong2 A0 = *(const ulonglong2*)&a_sh[kk][rg * 8];      // rows (0,1),(2,3)
            ulonglong2 A1 = *(const ulonglong2*)&a_sh[kk][rg * 8 + 4];  // rows (4,5),(6,7)
            float4 wv = *(const float4*)&w_sh[kk][cg * 4];
            ull w0 = bcast2(wv.x), w1 = bcast2(wv.y), w2 = bcast2(wv.z), w3 = bcast2(wv.w);
            fma2(acc[0][0], A0.x, w0); fma2(acc[0][1], A0.x, w1);
            fma2(acc[0][2], A0.x, w2); fma2(acc[0][3], A0.x, w3);
            fma2(acc[1][0], A0.y, w0); fma2(acc[1][1], A0.y, w1);
            fma2(acc[1][2], A0.y, w2); fma2(acc[1][3], A0.y, w3);
            fma2(acc[2][0], A1.x, w0); fma2(acc[2][1], A1.x, w1);
            fma2(acc[2][2], A1.x, w2); fma2(acc[2][3], A1.x, w3);
            fma2(acc[3][0], A1.y, w0); fma2(acc[3][1], A1.y, w1);
            fma2(acc[3][2], A1.y, w2); fma2(acc[3][3], A1.y, w3);
        }
        __syncthreads();
    }
    float4 bi = *(const float4*)(bias + col0 + cg * 4);
    #pragma unroll
    for (int p = 0; p < 4; p++) {
        float2 c0 = unpack2(acc[p][0]), c1 = unpack2(acc[p][1]);
        float2 c2 = unpack2(acc[p][2]), c3 = unpack2(acc[p][3]);
        int re = row0 + rg * 8 + 2 * p;
        float4 oe = make_float4(c0.x + bi.x, c1.x + bi.y, c2.x + bi.z, c3.x + bi.w);
        float4 oo = make_float4(c0.y + bi.x, c1.y + bi.y, c2.y + bi.z, c3.y + bi.w);
        *(float4*)(C + ((size_t)b * rows + re)     * DD + col0 + cg * 4) = oe;
        *(float4*)(C + ((size_t)b * rows + re + 1) * DD + col0 + cg * 4) = oo;
    }
}

// ---------------- mid: uproj (256 blks) + usum (16 blks) + scores (128 blks) --------
__global__ __launch_bounds__(256) void k_mid(const float* __restrict__ W_h,
                                             const float* __restrict__ W_t)
{
    __shared__ __align__(16) char buf[33792];
    int blk = blockIdx.x;
    int tid = threadIdx.x;

    if (blk < 256) {
        // ---- uproj: u[s][b][h][m][:] = v_h[m] @ Wo_h ; 128x128 tile, K=32 ----
        int ct = blk & 1;
        int g = blk >> 1;
        int s = g >> 6, b = (g >> 3) & 7, h = g & 7;
        const float* Wo = (s ? W_t : W_h) + 3 * 65536 + h * DKK * DD;
        const float* V = g_v[s] + (size_t)b * MM * DD + h * DKK;
        int col0 = ct * 128;
        float (*a_sh)[132] = (float(*)[132])buf;                   // [k][row], 16896B
        float (*w_sh)[128] = (float(*)[128])(buf + 16896);         // [k][col], 16384B

        #pragma unroll
        for (int i = 0; i < 4; i++) {      // V slice 128x32 transposed
            int f = tid + i * 256;
            int r = f >> 3;
            int kq = (f & 7) * 4;
            float4 av = *(const float4*)(V + (size_t)r * DD + kq);
            a_sh[kq+0][r] = av.x; a_sh[kq+1][r] = av.y;
            a_sh[kq+2][r] = av.z; a_sh[kq+3][r] = av.w;
        }
        #pragma unroll
        for (int i = 0; i < 4; i++) {      // Wo slice 32x128
            int idx = tid + i * 256;
            int kk = idx >> 5;
            int dq = (idx & 31) * 4;
            *(float4*)&w_sh[kk][dq] = *(const float4*)(Wo + (size_t)kk * DD + col0 + dq);
        }
        __syncthreads();

        int rg = tid & 15;   // 16 row groups x 8 rows
        int cg = tid >> 4;   // 16 col groups x 8 cols
        ull acc[4][8];
        #pragma unroll
        for (int p = 0; p < 4; p++)
            #pragma unroll
            for (int c = 0; c < 8; c++) acc[p][c] = 0ull;
        #pragma unroll
        for (int kk = 0; kk < 32; kk++) {
            ulonglong2 A0 = *(const ulonglong2*)&a_sh[kk][rg * 8];
            ulonglong2 A1 = *(const ulonglong2*)&a_sh[kk][rg * 8 + 4];
            float4 wa = *(const float4*)&w_sh[kk][cg * 8];
            float4 wb = *(const float4*)&w_sh[kk][cg * 8 + 4];
            ull wp[8] = { bcast2(wa.x), bcast2(wa.y), bcast2(wa.z), bcast2(wa.w),
                          bcast2(wb.x), bcast2(wb.y), bcast2(wb.z), bcast2(wb.w) };
            #pragma unroll
            for (int c = 0; c < 8; c++) {
                fma2(acc[0][c], A0.x, wp[c]);
                fma2(acc[1][c], A0.y, wp[c]);
                fma2(acc[2][c], A1.x, wp[c]);
                fma2(acc[3][c], A1.y, wp[c]);
            }
        }
        float* U = g_u[s] + ((size_t)(b * HH + h) * MM) * DD;
        #pragma unroll
        for (int p = 0; p < 4; p++) {
            float2 u0 = unpack2(acc[p][0]), u1 = unpack2(acc[p][1]);
            float2 u2 = unpack2(acc[p][2]), u3 = unpack2(acc[p][3]);
            float2 u4 = unpack2(acc[p][4]), u5 = unpack2(acc[p][5]);
            float2 u6 = unpack2(acc[p][6]), u7 = unpack2(acc[p][7]);
            int re = rg * 8 + 2 * p;
            float* d0 = U + (size_t)re * DD + col0 + cg * 8;
            float* d1 = d0 + DD;
            *(float4*)(d0)     = make_float4(u0.x, u1.x, u2.x, u3.x);
            *(float4*)(d0 + 4) = make_float4(u4.x, u5.x, u6.x, u7.x);
            *(float4*)(d1)     = make_float4(u0.y, u1.y, u2.y, u3.y);
            *(float4*)(d1 + 4) = make_float4(u4.y, u5.y, u6.y, u7.y);
        }
    } else if (blk < 272) {
        // ---- usum[s][b][:] = (sum_m v[b,m,:]) @ Wo ----
        int id = blk - 256;
        int b = id & 7, s = id >> 3;
        const float* Wo = (s ? W_t : W_h) + 3 * 65536;
        float* vs = (float*)buf;
        int d = tid;
        const float* v = g_v[s] + (size_t)b * MM * DD;
        float sum = 0.f;
        for (int m = 0; m < MM; m++) sum += v[m * DD + d];
        vs[d] = sum;
        __syncthreads();
        float o = 0.f;
        for (int k = 0; k < DD; k++) o = fmaf(vs[k], Wo[(size_t)k * DD + d], o);
        g_usum[s][b * DD + d] = o;
    } else {
        // ---- scores: S[s][b][h][j][m] = q_j . k_m / sqrt(32) ----
        int t = blk - 272;
        int h = t & 7, b = (t >> 3) & 7, s = t >> 6;
        float (*qs)[DKK + 1] = (float(*)[DKK + 1])buf;
        float (*ks)[DKK + 1] = (float(*)[DKK + 1])(buf + EE * (DKK + 1) * 4);
        const float* q = g_q[s] + (size_t)b * EE * DD + h * DKK;
        const float* k = g_k[s] + (size_t)b * MM * DD + h * DKK;
        for (int i = tid; i < EE * DKK; i += 256) { int r = i >> 5, c = i & 31; qs[r][c] = q[r * DD + c]; }
        for (int i = tid; i < MM * DKK; i += 256) { int r = i >> 5, c = i & 31; ks[r][c] = k[r * DD + c]; }
        __syncthreads();
        int j = tid >> 2;
        float* Srow = g_S[s] + ((size_t)(b * HH + h) * EE + j) * MM;
        const float scale = 0.17677669529663687f;
        for (int m = (tid & 3); m < MM; m += 4) {
            float acc = 0.f;
            #pragma unroll
            for (int c = 0; c < DKK; c++) acc = fmaf(qs[j][c], ks[m][c], acc);
            Srow[m] = acc * scale;
        }
    }
}

// ---------------- main output: masked softmax + weighted-u (f32x2 accum) ----------
__global__ __launch_bounds__(256) void k_out(const float* __restrict__ b_h,
                                             const float* __restrict__ b_t,
                                             float* __restrict__ out)
{
    int i = blockIdx.x;
    int b = blockIdx.y;
    int s = blockIdx.z;
    const float* bo = (s ? b_t : b_h) + 3 * 256;
    float* outS = out + (size_t)s * SETHALF + (size_t)b * NPAIR * DD;
    int tid = threadIdx.x;
    int cnt = g_cnt[b * EE + i];

    if (cnt == 0) {
        int d = tid;
        float val = bo[d] + g_usum[s][b * DD + d] * (1.0f / 128.0f);
        for (int j = 0; j < EE; j++) {
            int pair = (s == 0) ? (i * EE + j) : (j * EE + i);
            outS[(size_t)pair * DD + d] = val;
        }
        return;
    }

    __shared__ float mx[HH][EE];
    __shared__ float rse[HH][EE];
    __shared__ float wsh[HH][CHUNK][EE];
    __shared__ int lst[MM];
    for (int t = tid; t < cnt; t += 256) lst[t] = g_list[(b * EE + i) * MM + t];
    __syncthreads();

    for (int task = tid; task < HH * EE; task += 256) {
        int h = task >> 6, j = task & 63;
        const float* Srow = g_S[s] + ((size_t)(b * HH + h) * EE + j) * MM;
        float m_ = -1e30f;
        for (int c = 0; c < cnt; c++) m_ = fmaxf(m_, Srow[lst[c]]);
        float se = 0.f;
        for (int c = 0; c < cnt; c++) se += __expf(Srow[lst[c]] - m_);
        mx[h][j] = m_;
        rse[h][j] = 1.0f / se;
    }
    __syncthreads();

    int dq = tid & 63;   // d = dq*4 .. dq*4+3  (as 2 f32x2 pairs)
    int jg = tid >> 6;   // j = jg*16 .. +15
    ull acc[16][2];
    #pragma unroll
    for (int jj = 0; jj < 16; jj++) { acc[jj][0] = 0ull; acc[jj][1] = 0ull; }

    for (int base = 0; base < cnt; base += CHUNK) {
        int cEnd = min(CHUNK, cnt - base);
        int ce64 = cEnd << 6;
        for (int t = tid; t < HH * ce64; t += 256) {
            int h = t / ce64;
            int rem = t - h * ce64;
            int c = rem >> 6;
            int j = rem & 63;
            int m_ = lst[base + c];
            float sv = g_S[s][((size_t)(b * HH + h) * EE + j) * MM + m_];
            wsh[h][c][j] = __expf(sv - mx[h][j]) * rse[h][j];
        }
        __syncthreads();
        for (int h = 0; h < HH; h++) {
            for (int c = 0; c < cEnd; c++) {
                int m_ = lst[base + c];
                ulonglong2 U = *(const ulonglong2*)(g_u[s] +
                        ((size_t)(b * HH + h) * MM + m_) * DD + dq * 4);
                const float* wrow = &wsh[h][c][jg * 16];
                #pragma unroll
                for (int jj = 0; jj < 16; jj++) {
                    ull wp = bcast2(wrow[jj]);
                    fma2(acc[jj][0], wp, U.x);
                    fma2(acc[jj][1], wp, U.y);
                }
            }
        }
        __syncthreads();
    }

    float4 bo4 = *(const float4*)(bo + dq * 4);
    #pragma unroll
    for (int jj = 0; jj < 16; jj++) {
        int j = jg * 16 + jj;
        int pair = (s == 0) ? (i * EE + j) : (j * EE + i);
        float2 p0 = unpack2(acc[jj][0]);
        float2 p1 = unpack2(acc[jj][1]);
        float4 o = make_float4(p0.x + bo4.x, p0.y + bo4.y, p1.x + bo4.z, p1.y + bo4.w);
        *(float4*)(outS + (size_t)pair * DD + dq * 4) = o;
    }
}

// ---------------- launch ----------------
extern "C" void kernel_launch(void* const* d_in, const int* in_sizes, int n_in,
                              void* d_out, int out_size) {
    const float* entities  = (const float*)d_in[0];
    const float* mentions  = (const float*)d_in[1];
    const float* sentences = (const float*)d_in[2];
    const int*   sent_ids  = (const int*)d_in[3];
    const int*   eid       = (const int*)d_in[4];
    const float* W_h       = (const float*)d_in[5];
    const float* b_h       = (const float*)d_in[6];
    const float* W_t       = (const float*)d_in[7];
    const float* b_t       = (const float*)d_in[8];
    float* out = (float*)d_out;

    k_prep<<<dim3(BB * MM + BB), 64>>>(sentences, sent_ids, eid);
    k_gemm_all<<<dim3(2, 10, BB), 256>>>(entities, mentions, W_h, b_h, W_t, b_t);
    k_mid<<<400, 256>>>(W_h, W_t);
    k_out<<<dim3(EE, BB, 2), 256>>>(b_h, b_t, out);
}